// round 8
// baseline (speedup 1.0000x reference)
#include <cuda_runtime.h>
#include <cuda_bf16.h>
#include <cuda_fp16.h>
#include <cstdint>

#define NB2 128   // persistent blocks in recurrent kernel (best measured)

// ------------------------------------------------------------------
// Device-global scratch (allocation-free)
// ------------------------------------------------------------------
__device__ float  d_Gx[(size_t)16384 * 4096];      // x@Wx + bias
__device__ __half d_H2h[(size_t)16384 * 1024];     // h fp16 [b*512+t][j] for final FC
__device__ __half d_Hts[(size_t)513 * 32 * 1024];  // h fp16 [t][b][k_perm]
__device__ __half d_xh[(size_t)16384 * 512];       // x converted to fp16
__device__ __half d_Wxh[(size_t)512 * 4096];       // fp16 input weights, k-pair interleaved
__device__ __half d_Wfch[(size_t)1024 * 512];      // fp16 W_fc, k-pair interleaved
__device__ float  d_bx[4096];                      // packed gate biases
__device__ unsigned d_cnt[512];                    // per-step arrival counters
__device__ unsigned d_flag;                        // release flag: last finished step+1

// ------------------------------------------------------------------
// Helpers
// ------------------------------------------------------------------
__device__ __forceinline__ void mma_f16(float c[4],
                                        unsigned a0, unsigned a1, unsigned a2, unsigned a3,
                                        unsigned b0, unsigned b1) {
    asm volatile(
        "mma.sync.aligned.m16n8k16.row.col.f32.f16.f16.f32 "
        "{%0,%1,%2,%3},{%4,%5,%6,%7},{%8,%9},{%0,%1,%2,%3};"
        : "+f"(c[0]), "+f"(c[1]), "+f"(c[2]), "+f"(c[3])
        : "r"(a0), "r"(a1), "r"(a2), "r"(a3), "r"(b0), "r"(b1));
}

__device__ __forceinline__ float tanh_a(float x) {
    float y;
    asm("tanh.approx.f32 %0, %1;" : "=f"(y) : "f"(x));
    return y;
}
__device__ __forceinline__ float sigm(float x) {
    return 0.5f * tanh_a(0.5f * x) + 0.5f;
}

// k-permutation of the fp16 h layout (verified in R5-R7)
__device__ __forceinline__ int perm32(int j) {
    int tig = (j & 7) >> 1;
    int a   = (j & 31) >> 4;
    return (j & ~31) + tig * 8 + a * 4 + (j & 1) + 2 * ((j & 15) >> 3);
}

// ------------------------------------------------------------------
// Init: zero h_0 slab, counters, and release flag (every launch/replay)
// ------------------------------------------------------------------
__global__ void init_kernel() {
    int idx = blockIdx.x * blockDim.x + threadIdx.x;
    if (idx < 16384) ((unsigned*)d_Hts)[idx] = 0u;   // 32768 halves
    if (idx < 512) d_cnt[idx] = 0u;
    if (idx == 0) d_flag = 0u;
}

// ------------------------------------------------------------------
// Convert x to fp16 (2 floats / thread)
// ------------------------------------------------------------------
__global__ void xconv_kernel(const float* __restrict__ x) {
    int idx = blockIdx.x * blockDim.x + threadIdx.x;
    float2 v = *(const float2*)(x + 2 * (size_t)idx);
    ((__half2*)d_xh)[idx] = __floats2half2_rn(v.x, v.y);
}

// ------------------------------------------------------------------
// Pack fp16 Wx (k-pair interleaved, N=4096) + gate biases
// ------------------------------------------------------------------
__global__ void pack_kernel(const float* __restrict__ Wf, const float* __restrict__ Wi,
                            const float* __restrict__ Wg, const float* __restrict__ Wo,
                            const float* __restrict__ bf, const float* __restrict__ bi,
                            const float* __restrict__ bg, const float* __restrict__ bo) {
    int idx = blockIdx.x * blockDim.x + threadIdx.x;
    if (idx < 512 * 1024) {
        int k = idx >> 10, j = idx & 1023;
        size_t base = ((size_t)(k >> 1) * 4096) * 2 + (k & 1);
        d_Wxh[base + (size_t)(j) * 2]        = __float2half_rn(Wf[idx]);
        d_Wxh[base + (size_t)(j + 1024) * 2] = __float2half_rn(Wi[idx]);
        d_Wxh[base + (size_t)(j + 2048) * 2] = __float2half_rn(Wg[idx]);
        d_Wxh[base + (size_t)(j + 3072) * 2] = __float2half_rn(Wo[idx]);
    }
    if (idx < 1024) {
        d_bx[idx]        = bf[idx];
        d_bx[idx + 1024] = bi[idx];
        d_bx[idx + 2048] = bg[idx];
        d_bx[idx + 3072] = bo[idx];
    }
}

// ------------------------------------------------------------------
// Pack fp16 W_fc (k-pair interleaved, N=512)
// ------------------------------------------------------------------
__global__ void packfc_kernel(const float* __restrict__ Wfc) {
    int idx = blockIdx.x * blockDim.x + threadIdx.x;   // 0 .. 524287
    int k = idx >> 9, j = idx & 511;
    d_Wfch[(((size_t)(k >> 1) * 512) + j) * 2 + (k & 1)] = __float2half_rn(Wfc[idx]);
}

// ------------------------------------------------------------------
// Generic fp16 GEMM: C[M,N] = A[M,K] @ B[K,N] + bias[N]
// A row-major fp16, B k-pair interleaved fp16, C fp32.
// 128x128x32 tiles, 8 warps (warp 64x32). M%128==0, N%128==0, K%32==0.
// ------------------------------------------------------------------
__global__ void __launch_bounds__(256) gemm_f16_bias(
    const __half* __restrict__ A, const __half* __restrict__ Bp,
    const float* __restrict__ bias, float* __restrict__ C,
    int M, int N, int K) {
    __shared__ __half sAh[128 * 40];   // 128 rows x 32 halves (+8 pad)
    __shared__ __half sBh[16 * 272];   // 16 k2-rows x 128 cols x 2 (+16 pad)

    const int tid = threadIdx.x;
    const int w = tid >> 5, lane = tid & 31;
    const int g = lane >> 2, tig = lane & 3;
    const int wm = (w >> 2) * 64, wn = (w & 3) * 32;
    const int m0 = blockIdx.y * 128, n0 = blockIdx.x * 128;

    float Cr[4][4][4];
#pragma unroll
    for (int a = 0; a < 4; a++)
#pragma unroll
        for (int b = 0; b < 4; b++)
#pragma unroll
            for (int c = 0; c < 4; c++) Cr[a][b][c] = 0.f;

    const int nk = K / 32;
    for (int kc = 0; kc < nk; kc++) {
        const int k0 = kc * 32;
        __syncthreads();
#pragma unroll
        for (int i = 0; i < 2; i++) {
            int lin = tid + i * 256;
            int r = lin >> 2, q = lin & 3;
            *(uint4*)(sAh + r * 40 + q * 8) =
                *(const uint4*)(A + (size_t)(m0 + r) * K + k0 + q * 8);
        }
#pragma unroll
        for (int i = 0; i < 2; i++) {
            int lin = tid + i * 256;
            int k2r = lin >> 5, c4 = lin & 31;
            *(uint4*)(sBh + k2r * 272 + c4 * 8) =
                *(const uint4*)(Bp + ((size_t)((k0 >> 1) + k2r) * N + n0 + c4 * 4) * 2);
        }
        __syncthreads();

#pragma unroll
        for (int kt = 0; kt < 2; kt++) {
            unsigned bf_[4][2];
#pragma unroll
            for (int nt = 0; nt < 4; nt++) {
                int jc = wn + nt * 8 + g;
                bf_[nt][0] = *(const unsigned*)(sBh + (kt * 8 + tig) * 272 + jc * 2);
                bf_[nt][1] = *(const unsigned*)(sBh + (kt * 8 + tig + 4) * 272 + jc * 2);
            }
#pragma unroll
            for (int mt = 0; mt < 4; mt++) {
                int ro = (wm + mt * 16 + g) * 40 + kt * 16 + 2 * tig;
                unsigned a0 = *(const unsigned*)(sAh + ro);
                unsigned a1 = *(const unsigned*)(sAh + ro + 8 * 40);
                unsigned a2 = *(const unsigned*)(sAh + ro + 8);
                unsigned a3 = *(const unsigned*)(sAh + ro + 8 * 40 + 8);
#pragma unroll
                for (int nt = 0; nt < 4; nt++)
                    mma_f16(Cr[mt][nt], a0, a1, a2, a3, bf_[nt][0], bf_[nt][1]);
            }
        }
    }

#pragma unroll
    for (int mt = 0; mt < 4; mt++) {
#pragma unroll
        for (int nt = 0; nt < 4; nt++) {
            int row = m0 + wm + mt * 16 + g;
            int col = n0 + wn + nt * 8 + 2 * tig;
            float bx = bias[col], by = bias[col + 1];
            float2 v0 = make_float2(Cr[mt][nt][0] + bx, Cr[mt][nt][1] + by);
            float2 v1 = make_float2(Cr[mt][nt][2] + bx, Cr[mt][nt][3] + by);
            *(float2*)(C + (size_t)row * N + col) = v0;
            *(float2*)(C + (size_t)(row + 8) * N + col) = v1;
        }
    }
}

// ------------------------------------------------------------------
// Persistent recurrent kernel. 128 blocks x 512 threads (16 warps).
// Compute structure = R5/R7 (best measured). NEW synchronization:
//  - per-warp flag polling (ld.acquire) instead of tid0-poll + block BAR
//  - arrival: state-only named barrier + tid0 atom.acq_rel; LAST arriver
//    publishes d_flag = t+1 with st.release
//  - Gx for step t+1 prefetched right after the h store (hidden by wait)
//  - tanh.approx.f32 gate nonlinearities
// Hazard ordering: a warp passes poll(t+1) only after ALL blocks' state
// threads arrived at t, which is after their sPart reads and h stores,
// so sPart overwrite and h(t+1) reads are safe without extra BARs.
// ------------------------------------------------------------------
__global__ void __launch_bounds__(512) lstm_rec(
    const float* __restrict__ Wf, const float* __restrict__ Wi,
    const float* __restrict__ Wg, const float* __restrict__ Wo) {
    extern __shared__ float sPart[];   // 16 regions x 32 rows x 36 floats

    const int tid = threadIdx.x;
    const int w = tid >> 5, lane = tid & 31;
    const int g = lane >> 2, tig = lane & 3;
    const int kw = w * 64;
    const int bk = blockIdx.x;

    // ---- Preload weights as fp16x2 B-fragments (true k order) ----
    const float* Wp[4] = {Wf, Wi, Wg, Wo};
    unsigned Wr[4][4][2];
#pragma unroll
    for (int kt = 0; kt < 4; kt++) {
#pragma unroll
        for (int nt = 0; nt < 4; nt++) {
            const float* ws = Wp[nt] + (size_t)(512 + kw + kt * 16 + 2 * tig) * 1024 + bk * 8 + g;
            __half2 lo = __floats2half2_rn(__ldg(ws), __ldg(ws + 1024));
            __half2 hi = __floats2half2_rn(__ldg(ws + 8 * 1024), __ldg(ws + 9 * 1024));
            Wr[kt][nt][0] = *(unsigned*)&lo;
            Wr[kt][nt][1] = *(unsigned*)&hi;
        }
    }

    // State-thread mapping (first 256 threads): b = tid/8, uu = tid%8
    const int b_ = (tid >> 3) & 31, uu = tid & 7;
    const bool is_state = tid < 256;
    float creg = 0.f;
    const int j = bk * 8 + uu;
    const int ppos = perm32(j);

    // Incremented pointers
    const __half* hrd = d_Hts + kw + tig * 8;                           // += 32768
    __half* hwr = d_Hts + 32768 + (size_t)b_ * 1024 + ppos;             // += 32768
    const float* gxp = d_Gx + (size_t)(b_ * 512) * 4096 + bk * 8 + uu;  // += 4096
    __half* h2p = d_H2h + (size_t)(b_ * 512) * 1024 + bk * 8 + uu;      // += 1024
    unsigned* cntp = d_cnt;                                              // += 1
    unsigned* flagp = &d_flag;

    // Prefetch Gx for step 0
    float gx0 = 0.f, gx1 = 0.f, gx2 = 0.f, gx3 = 0.f;
    if (is_state) {
        gx0 = __ldcs(gxp);
        gx1 = __ldcs(gxp + 1024);
        gx2 = __ldcs(gxp + 2048);
        gx3 = __ldcs(gxp + 3072);
    }

    for (int t = 0; t < 512; t++) {
        // ---- Per-warp wait for global release of step t ----
        if (t > 0) {
            unsigned v;
            do {
                asm volatile("ld.acquire.gpu.u32 %0, [%1];"
                             : "=r"(v) : "l"(flagp) : "memory");
            } while (v < (unsigned)t);
        }

        // ---- Front-batched h loads: 8 x LDG.128 (max MLP) ----
        uint4 V[2][2][2];   // [kb][mt][row g / g+8]
#pragma unroll
        for (int kb = 0; kb < 2; kb++)
#pragma unroll
            for (int mt = 0; mt < 2; mt++) {
                V[kb][mt][0] = __ldcg((const uint4*)(hrd + kb * 32 + (mt * 16 + g) * 1024));
                V[kb][mt][1] = __ldcg((const uint4*)(hrd + kb * 32 + (mt * 16 + g + 8) * 1024));
            }

        // ---- h_t @ Wh_slice (fp16 HMMA, fp32 accum) ----
        float Cr[2][4][4];
#pragma unroll
        for (int mt = 0; mt < 2; mt++)
#pragma unroll
            for (int nt = 0; nt < 4; nt++)
#pragma unroll
                for (int c = 0; c < 4; c++) Cr[mt][nt][c] = 0.f;

#pragma unroll
        for (int kb = 0; kb < 2; kb++) {
#pragma unroll
            for (int mt = 0; mt < 2; mt++) {
                const uint4& v0 = V[kb][mt][0];
                const uint4& v1 = V[kb][mt][1];
#pragma unroll
                for (int nt = 0; nt < 4; nt++)
                    mma_f16(Cr[mt][nt], v0.x, v1.x, v0.y, v1.y,
                            Wr[2 * kb][nt][0], Wr[2 * kb][nt][1]);
#pragma unroll
                for (int nt = 0; nt < 4; nt++)
                    mma_f16(Cr[mt][nt], v0.z, v1.z, v0.w, v1.w,
                            Wr[2 * kb + 1][nt][0], Wr[2 * kb + 1][nt][1]);
            }
        }

        // ---- Write partials: region w, gate-contiguous layout ----
        {
            float* sp = sPart + w * 1152;
#pragma unroll
            for (int mt = 0; mt < 2; mt++) {
#pragma unroll
                for (int nt = 0; nt < 4; nt++) {
                    int row = mt * 16 + g, c = 2 * tig;
                    sp[row * 36 + c * 4 + nt]             = Cr[mt][nt][0];
                    sp[row * 36 + (c + 1) * 4 + nt]       = Cr[mt][nt][1];
                    sp[(row + 8) * 36 + c * 4 + nt]       = Cr[mt][nt][2];
                    sp[(row + 8) * 36 + (c + 1) * 4 + nt] = Cr[mt][nt][3];
                }
            }
        }
        __syncthreads();   // partials ready for the reduce

        // ---- State epilogue (warps 0-7 only) ----
        if (is_state) {
            const float4* rp = (const float4*)sPart + (b_ * 9 + uu);
            float4 s0 = rp[0], s1 = rp[288];
#pragma unroll
            for (int r = 2; r < 16; r += 2) {
                float4 a = rp[r * 288], b = rp[(r + 1) * 288];
                s0.x += a.x; s0.y += a.y; s0.z += a.z; s0.w += a.w;
                s1.x += b.x; s1.y += b.y; s1.z += b.z; s1.w += b.w;
            }
            float F = s0.x + s1.x + gx0;
            float I = s0.y + s1.y + gx1;
            float G = s0.z + s1.z + gx2;
            float O = s0.w + s1.w + gx3;
            creg = sigm(F) * creg + sigm(I) * tanh_a(G);
            float h = sigm(O) * tanh_a(creg);

            __half hh = __float2half_rn(h);
            *hwr = hh;
            *h2p = hh;

            // Prefetch Gx for step t+1 (hidden behind the barrier wait)
            gxp += 4096;
            if (t < 511) {
                gx0 = __ldcs(gxp);
                gx1 = __ldcs(gxp + 1024);
                gx2 = __ldcs(gxp + 2048);
                gx3 = __ldcs(gxp + 3072);
            }

            // Arrival: state-only named barrier, then one atomic per block.
            asm volatile("bar.sync 1, 256;" ::: "memory");
            if (tid == 0) {
                unsigned ret;
                asm volatile("atom.acq_rel.gpu.add.u32 %0, [%1], %2;"
                             : "=r"(ret) : "l"(cntp), "r"(1u) : "memory");
                if (ret + 1u == NB2) {
                    asm volatile("st.release.gpu.u32 [%0], %1;"
                                 :: "l"(flagp), "r"((unsigned)(t + 1)) : "memory");
                }
            }
        }

        hrd += 32768; hwr += 32768; h2p += 1024; cntp += 1;
    }
}

// ------------------------------------------------------------------
// Launch sequence (graph-capturable: kernel launches only)
// ------------------------------------------------------------------
extern "C" void kernel_launch(void* const* d_in, const int* in_sizes, int n_in,
                              void* d_out, int out_size) {
    const float* x    = (const float*)d_in[0];
    const float* W_f  = (const float*)d_in[1];
    const float* b_f  = (const float*)d_in[2];
    const float* W_i  = (const float*)d_in[3];
    const float* b_i  = (const float*)d_in[4];
    const float* W_g  = (const float*)d_in[5];
    const float* b_g  = (const float*)d_in[6];
    const float* W_o  = (const float*)d_in[7];
    const float* b_o  = (const float*)d_in[8];
    const float* W_fc = (const float*)d_in[9];
    const float* b_fc = (const float*)d_in[10];
    float* out = (float*)d_out;

    void *pGx, *pH2h, *pXh, *pWxh, *pWfch, *pbx;
    cudaGetSymbolAddress(&pGx, d_Gx);
    cudaGetSymbolAddress(&pH2h, d_H2h);
    cudaGetSymbolAddress(&pXh, d_xh);
    cudaGetSymbolAddress(&pWxh, d_Wxh);
    cudaGetSymbolAddress(&pWfch, d_Wfch);
    cudaGetSymbolAddress(&pbx, d_bx);

    static bool attr_set = false;
    if (!attr_set) {
        cudaFuncSetAttribute(lstm_rec, cudaFuncAttributeMaxDynamicSharedMemorySize,
                             16 * 1152 * 4);
        attr_set = true;
    }

    init_kernel<<<128, 256>>>();
    xconv_kernel<<<16384, 256>>>(x);
    pack_kernel<<<2048, 256>>>(W_f, W_i, W_g, W_o, b_f, b_i, b_g, b_o);
    packfc_kernel<<<2048, 256>>>(W_fc);

    // Phase 1: Gx = x @ Wx + bx   (fp16 HMMA, M=16384, N=4096, K=512)
    gemm_f16_bias<<<dim3(32, 128), 256>>>(
        (const __half*)pXh, (const __half*)pWxh, (const float*)pbx,
        (float*)pGx, 16384, 4096, 512);

    // Phase 2: recurrence (persistent, 128 blocks)
    lstm_rec<<<NB2, 512, 16 * 1152 * 4>>>(W_f, W_i, W_g, W_o);

    // Phase 3: out = H2h @ W_fc + b_fc   (fp16 HMMA, M=16384, N=512, K=1024)
    gemm_f16_bias<<<dim3(4, 128), 256>>>(
        (const __half*)pH2h, (const __half*)pWfch, b_fc,
        out, 16384, 512, 1024);
}

// round 9
// speedup vs baseline: 1.2252x; 1.2252x over previous
#include <cuda_runtime.h>
#include <cuda_bf16.h>
#include <cuda_fp16.h>
#include <cstdint>

#define NB2 128   // persistent blocks in recurrent kernel (best measured)

// ------------------------------------------------------------------
// Device-global scratch (allocation-free)
// ------------------------------------------------------------------
__device__ float  d_Gx[(size_t)16384 * 4096];      // x@Wx + bias
__device__ __half d_H2h[(size_t)16384 * 1024];     // h fp16 [b*512+t][j] for final FC
__device__ __half d_Hts[(size_t)513 * 32 * 1024];  // h fp16 [t][b][k_perm]
__device__ __half d_xh[(size_t)16384 * 512];       // x converted to fp16
__device__ __half d_Wxh[(size_t)512 * 4096];       // fp16 input weights, k-pair interleaved
__device__ __half d_Wfch[(size_t)1024 * 512];      // fp16 W_fc, k-pair interleaved
__device__ float  d_bx[4096];                      // packed gate biases
__device__ unsigned d_cnt[512];                    // per-step arrival counters (atomics only)
__device__ unsigned d_flag;                        // release flag (polled; written once/step)

// ------------------------------------------------------------------
// Helpers
// ------------------------------------------------------------------
__device__ __forceinline__ void mma_f16(float c[4],
                                        unsigned a0, unsigned a1, unsigned a2, unsigned a3,
                                        unsigned b0, unsigned b1) {
    asm volatile(
        "mma.sync.aligned.m16n8k16.row.col.f32.f16.f16.f32 "
        "{%0,%1,%2,%3},{%4,%5,%6,%7},{%8,%9},{%0,%1,%2,%3};"
        : "+f"(c[0]), "+f"(c[1]), "+f"(c[2]), "+f"(c[3])
        : "r"(a0), "r"(a1), "r"(a2), "r"(a3), "r"(b0), "r"(b1));
}

__device__ __forceinline__ float tanh_a(float x) {
    float y;
    asm("tanh.approx.f32 %0, %1;" : "=f"(y) : "f"(x));
    return y;
}
__device__ __forceinline__ float sigm(float x) {
    return 0.5f * tanh_a(0.5f * x) + 0.5f;
}

// k-permutation of the fp16 h layout (verified in R5-R8)
__device__ __forceinline__ int perm32(int j) {
    int tig = (j & 7) >> 1;
    int a   = (j & 31) >> 4;
    return (j & ~15 & ~16) + (j & 16) + tig * 8 + a * 4 + (j & 1) + 2 * ((j & 15) >> 3);
}

// ------------------------------------------------------------------
// Init: zero h_0 slab, counters, and release flag (every launch/replay)
// ------------------------------------------------------------------
__global__ void init_kernel() {
    int idx = blockIdx.x * blockDim.x + threadIdx.x;
    if (idx < 16384) ((unsigned*)d_Hts)[idx] = 0u;   // 32768 halves
    if (idx < 512) d_cnt[idx] = 0u;
    if (idx == 0) d_flag = 0u;
}

// ------------------------------------------------------------------
// Convert x to fp16 (2 floats / thread)
// ------------------------------------------------------------------
__global__ void xconv_kernel(const float* __restrict__ x) {
    int idx = blockIdx.x * blockDim.x + threadIdx.x;
    float2 v = *(const float2*)(x + 2 * (size_t)idx);
    ((__half2*)d_xh)[idx] = __floats2half2_rn(v.x, v.y);
}

// ------------------------------------------------------------------
// Pack fp16 Wx (k-pair interleaved, N=4096) + gate biases
// ------------------------------------------------------------------
__global__ void pack_kernel(const float* __restrict__ Wf, const float* __restrict__ Wi,
                            const float* __restrict__ Wg, const float* __restrict__ Wo,
                            const float* __restrict__ bf, const float* __restrict__ bi,
                            const float* __restrict__ bg, const float* __restrict__ bo) {
    int idx = blockIdx.x * blockDim.x + threadIdx.x;
    if (idx < 512 * 1024) {
        int k = idx >> 10, j = idx & 1023;
        size_t base = ((size_t)(k >> 1) * 4096) * 2 + (k & 1);
        d_Wxh[base + (size_t)(j) * 2]        = __float2half_rn(Wf[idx]);
        d_Wxh[base + (size_t)(j + 1024) * 2] = __float2half_rn(Wi[idx]);
        d_Wxh[base + (size_t)(j + 2048) * 2] = __float2half_rn(Wg[idx]);
        d_Wxh[base + (size_t)(j + 3072) * 2] = __float2half_rn(Wo[idx]);
    }
    if (idx < 1024) {
        d_bx[idx]        = bf[idx];
        d_bx[idx + 1024] = bi[idx];
        d_bx[idx + 2048] = bg[idx];
        d_bx[idx + 3072] = bo[idx];
    }
}

// ------------------------------------------------------------------
// Pack fp16 W_fc (k-pair interleaved, N=512)
// ------------------------------------------------------------------
__global__ void packfc_kernel(const float* __restrict__ Wfc) {
    int idx = blockIdx.x * blockDim.x + threadIdx.x;   // 0 .. 524287
    int k = idx >> 9, j = idx & 511;
    d_Wfch[(((size_t)(k >> 1) * 512) + j) * 2 + (k & 1)] = __float2half_rn(Wfc[idx]);
}

// ------------------------------------------------------------------
// Generic fp16 GEMM: C[M,N] = A[M,K] @ B[K,N] + bias[N]
// A row-major fp16, B k-pair interleaved fp16, C fp32.
// 128x128x32 tiles, 8 warps (warp 64x32). M%128==0, N%128==0, K%32==0.
// ------------------------------------------------------------------
__global__ void __launch_bounds__(256) gemm_f16_bias(
    const __half* __restrict__ A, const __half* __restrict__ Bp,
    const float* __restrict__ bias, float* __restrict__ C,
    int M, int N, int K) {
    __shared__ __half sAh[128 * 40];   // 128 rows x 32 halves (+8 pad)
    __shared__ __half sBh[16 * 272];   // 16 k2-rows x 128 cols x 2 (+16 pad)

    const int tid = threadIdx.x;
    const int w = tid >> 5, lane = tid & 31;
    const int g = lane >> 2, tig = lane & 3;
    const int wm = (w >> 2) * 64, wn = (w & 3) * 32;
    const int m0 = blockIdx.y * 128, n0 = blockIdx.x * 128;

    float Cr[4][4][4];
#pragma unroll
    for (int a = 0; a < 4; a++)
#pragma unroll
        for (int b = 0; b < 4; b++)
#pragma unroll
            for (int c = 0; c < 4; c++) Cr[a][b][c] = 0.f;

    const int nk = K / 32;
    for (int kc = 0; kc < nk; kc++) {
        const int k0 = kc * 32;
        __syncthreads();
#pragma unroll
        for (int i = 0; i < 2; i++) {
            int lin = tid + i * 256;
            int r = lin >> 2, q = lin & 3;
            *(uint4*)(sAh + r * 40 + q * 8) =
                *(const uint4*)(A + (size_t)(m0 + r) * K + k0 + q * 8);
        }
#pragma unroll
        for (int i = 0; i < 2; i++) {
            int lin = tid + i * 256;
            int k2r = lin >> 5, c4 = lin & 31;
            *(uint4*)(sBh + k2r * 272 + c4 * 8) =
                *(const uint4*)(Bp + ((size_t)((k0 >> 1) + k2r) * N + n0 + c4 * 4) * 2);
        }
        __syncthreads();

#pragma unroll
        for (int kt = 0; kt < 2; kt++) {
            unsigned bf_[4][2];
#pragma unroll
            for (int nt = 0; nt < 4; nt++) {
                int jc = wn + nt * 8 + g;
                bf_[nt][0] = *(const unsigned*)(sBh + (kt * 8 + tig) * 272 + jc * 2);
                bf_[nt][1] = *(const unsigned*)(sBh + (kt * 8 + tig + 4) * 272 + jc * 2);
            }
#pragma unroll
            for (int mt = 0; mt < 4; mt++) {
                int ro = (wm + mt * 16 + g) * 40 + kt * 16 + 2 * tig;
                unsigned a0 = *(const unsigned*)(sAh + ro);
                unsigned a1 = *(const unsigned*)(sAh + ro + 8 * 40);
                unsigned a2 = *(const unsigned*)(sAh + ro + 8);
                unsigned a3 = *(const unsigned*)(sAh + ro + 8 * 40 + 8);
#pragma unroll
                for (int nt = 0; nt < 4; nt++)
                    mma_f16(Cr[mt][nt], a0, a1, a2, a3, bf_[nt][0], bf_[nt][1]);
            }
        }
    }

#pragma unroll
    for (int mt = 0; mt < 4; mt++) {
#pragma unroll
        for (int nt = 0; nt < 4; nt++) {
            int row = m0 + wm + mt * 16 + g;
            int col = n0 + wn + nt * 8 + 2 * tig;
            float bx = bias[col], by = bias[col + 1];
            float2 v0 = make_float2(Cr[mt][nt][0] + bx, Cr[mt][nt][1] + by);
            float2 v1 = make_float2(Cr[mt][nt][2] + bx, Cr[mt][nt][3] + by);
            *(float2*)(C + (size_t)row * N + col) = v0;
            *(float2*)(C + (size_t)(row + 8) * N + col) = v1;
        }
    }
}

// ------------------------------------------------------------------
// Persistent recurrent kernel. 128 blocks x 512 threads (16 warps).
// Compute structure = R5/R7 (best measured). Synchronization = R7's
// block-level scheme (tid0-only global traffic; poll population O(blocks)),
// with R8's orthogonal wins kept:
//  - arrivals hit d_cnt[t] (atomics), tid0 POLLS d_flag — written ONCE
//    per step by the last arriver (no poll/atomic line contention)
//  - tanh.approx.f32 gates
//  - Gx(t+1) prefetched after the h store
// ------------------------------------------------------------------
__global__ void __launch_bounds__(512) lstm_rec(
    const float* __restrict__ Wf, const float* __restrict__ Wi,
    const float* __restrict__ Wg, const float* __restrict__ Wo) {
    extern __shared__ float sPart[];   // 16 regions x 32 rows x 36 floats

    const int tid = threadIdx.x;
    const int w = tid >> 5, lane = tid & 31;
    const int g = lane >> 2, tig = lane & 3;
    const int kw = w * 64;
    const int bk = blockIdx.x;

    // ---- Preload weights as fp16x2 B-fragments (true k order) ----
    const float* Wp[4] = {Wf, Wi, Wg, Wo};
    unsigned Wr[4][4][2];
#pragma unroll
    for (int kt = 0; kt < 4; kt++) {
#pragma unroll
        for (int nt = 0; nt < 4; nt++) {
            const float* ws = Wp[nt] + (size_t)(512 + kw + kt * 16 + 2 * tig) * 1024 + bk * 8 + g;
            __half2 lo = __floats2half2_rn(__ldg(ws), __ldg(ws + 1024));
            __half2 hi = __floats2half2_rn(__ldg(ws + 8 * 1024), __ldg(ws + 9 * 1024));
            Wr[kt][nt][0] = *(unsigned*)&lo;
            Wr[kt][nt][1] = *(unsigned*)&hi;
        }
    }

    // State-thread mapping (first 256 threads): b = tid/8, uu = tid%8
    const int b_ = (tid >> 3) & 31, uu = tid & 7;
    const bool is_state = tid < 256;
    float creg = 0.f;
    const int j = bk * 8 + uu;
    // permuted position (identical formula to R5-R8's perm32(j))
    const int ppos = (j & ~31) + ((j & 7) >> 1) * 8 + ((j & 31) >> 4) * 4
                     + (j & 1) + 2 * ((j & 15) >> 3);

    // Incremented pointers
    const __half* hrd = d_Hts + kw + tig * 8;                           // += 32768
    __half* hwr = d_Hts + 32768 + (size_t)b_ * 1024 + ppos;             // += 32768
    const float* gxp = d_Gx + (size_t)(b_ * 512) * 4096 + bk * 8 + uu;  // += 4096
    __half* h2p = d_H2h + (size_t)(b_ * 512) * 1024 + bk * 8 + uu;      // += 1024
    unsigned* cntp = d_cnt;                                              // += 1
    unsigned* flagp = &d_flag;

    // Prefetch Gx for step 0
    float gx0 = 0.f, gx1 = 0.f, gx2 = 0.f, gx3 = 0.f;
    if (is_state) {
        gx0 = __ldcs(gxp);
        gx1 = __ldcs(gxp + 1024);
        gx2 = __ldcs(gxp + 2048);
        gx3 = __ldcs(gxp + 3072);
    }

    for (int t = 0; t < 512; t++) {
        // ---- Front-batched h loads: 8 x LDG.128 (max MLP) ----
        uint4 V[2][2][2];   // [kb][mt][row g / g+8]
#pragma unroll
        for (int kb = 0; kb < 2; kb++)
#pragma unroll
            for (int mt = 0; mt < 2; mt++) {
                V[kb][mt][0] = __ldcg((const uint4*)(hrd + kb * 32 + (mt * 16 + g) * 1024));
                V[kb][mt][1] = __ldcg((const uint4*)(hrd + kb * 32 + (mt * 16 + g + 8) * 1024));
            }

        // ---- h_t @ Wh_slice (fp16 HMMA, fp32 accum) ----
        float Cr[2][4][4];
#pragma unroll
        for (int mt = 0; mt < 2; mt++)
#pragma unroll
            for (int nt = 0; nt < 4; nt++)
#pragma unroll
                for (int c = 0; c < 4; c++) Cr[mt][nt][c] = 0.f;

#pragma unroll
        for (int kb = 0; kb < 2; kb++) {
#pragma unroll
            for (int mt = 0; mt < 2; mt++) {
                const uint4& v0 = V[kb][mt][0];
                const uint4& v1 = V[kb][mt][1];
#pragma unroll
                for (int nt = 0; nt < 4; nt++)
                    mma_f16(Cr[mt][nt], v0.x, v1.x, v0.y, v1.y,
                            Wr[2 * kb][nt][0], Wr[2 * kb][nt][1]);
#pragma unroll
                for (int nt = 0; nt < 4; nt++)
                    mma_f16(Cr[mt][nt], v0.z, v1.z, v0.w, v1.w,
                            Wr[2 * kb + 1][nt][0], Wr[2 * kb + 1][nt][1]);
            }
        }

        // ---- Write partials: region w, gate-contiguous layout ----
        {
            float* sp = sPart + w * 1152;
#pragma unroll
            for (int mt = 0; mt < 2; mt++) {
#pragma unroll
                for (int nt = 0; nt < 4; nt++) {
                    int row = mt * 16 + g, c = 2 * tig;
                    sp[row * 36 + c * 4 + nt]             = Cr[mt][nt][0];
                    sp[row * 36 + (c + 1) * 4 + nt]       = Cr[mt][nt][1];
                    sp[(row + 8) * 36 + c * 4 + nt]       = Cr[mt][nt][2];
                    sp[(row + 8) * 36 + (c + 1) * 4 + nt] = Cr[mt][nt][3];
                }
            }
        }
        __syncthreads();

        // ---- Final reduce (16 x LDS.128) + gates + state update ----
        if (is_state) {
            const float4* rp = (const float4*)sPart + (b_ * 9 + uu);
            float4 s0 = rp[0], s1 = rp[288];
#pragma unroll
            for (int r = 2; r < 16; r += 2) {
                float4 a = rp[r * 288], b = rp[(r + 1) * 288];
                s0.x += a.x; s0.y += a.y; s0.z += a.z; s0.w += a.w;
                s1.x += b.x; s1.y += b.y; s1.z += b.z; s1.w += b.w;
            }
            float F = s0.x + s1.x + gx0;
            float I = s0.y + s1.y + gx1;
            float G = s0.z + s1.z + gx2;
            float O = s0.w + s1.w + gx3;
            creg = sigm(F) * creg + sigm(I) * tanh_a(G);
            float h = sigm(O) * tanh_a(creg);

            __half hh = __float2half_rn(h);
            *hwr = hh;
            *h2p = hh;

            // Prefetch Gx for step t+1 (hidden behind the barrier)
            gxp += 4096;
            if (t < 511) {
                gx0 = __ldcs(gxp);
                gx1 = __ldcs(gxp + 1024);
                gx2 = __ldcs(gxp + 2048);
                gx3 = __ldcs(gxp + 3072);
            }
        }
        __syncthreads();   // h stores + sPart reads complete

        // ---- Grid barrier: tid0 arrives on cnt, polls write-once flag ----
        if (tid == 0) {
            unsigned ret;
            asm volatile("atom.acq_rel.gpu.add.u32 %0, [%1], %2;"
                         : "=r"(ret) : "l"(cntp), "r"(1u) : "memory");
            if (ret + 1u == NB2) {
                asm volatile("st.release.gpu.u32 [%0], %1;"
                             :: "l"(flagp), "r"((unsigned)(t + 1)) : "memory");
            } else {
                unsigned v;
                do {
                    asm volatile("ld.acquire.gpu.u32 %0, [%1];"
                                 : "=r"(v) : "l"(flagp) : "memory");
                } while (v < (unsigned)(t + 1));
            }
        }
        __syncthreads();

        hrd += 32768; hwr += 32768; h2p += 1024; cntp += 1;
    }
}

// ------------------------------------------------------------------
// Launch sequence (graph-capturable: kernel launches only)
// ------------------------------------------------------------------
extern "C" void kernel_launch(void* const* d_in, const int* in_sizes, int n_in,
                              void* d_out, int out_size) {
    const float* x    = (const float*)d_in[0];
    const float* W_f  = (const float*)d_in[1];
    const float* b_f  = (const float*)d_in[2];
    const float* W_i  = (const float*)d_in[3];
    const float* b_i  = (const float*)d_in[4];
    const float* W_g  = (const float*)d_in[5];
    const float* b_g  = (const float*)d_in[6];
    const float* W_o  = (const float*)d_in[7];
    const float* b_o  = (const float*)d_in[8];
    const float* W_fc = (const float*)d_in[9];
    const float* b_fc = (const float*)d_in[10];
    float* out = (float*)d_out;

    void *pGx, *pH2h, *pXh, *pWxh, *pWfch, *pbx;
    cudaGetSymbolAddress(&pGx, d_Gx);
    cudaGetSymbolAddress(&pH2h, d_H2h);
    cudaGetSymbolAddress(&pXh, d_xh);
    cudaGetSymbolAddress(&pWxh, d_Wxh);
    cudaGetSymbolAddress(&pWfch, d_Wfch);
    cudaGetSymbolAddress(&pbx, d_bx);

    static bool attr_set = false;
    if (!attr_set) {
        cudaFuncSetAttribute(lstm_rec, cudaFuncAttributeMaxDynamicSharedMemorySize,
                             16 * 1152 * 4);
        attr_set = true;
    }

    init_kernel<<<128, 256>>>();
    xconv_kernel<<<16384, 256>>>(x);
    pack_kernel<<<2048, 256>>>(W_f, W_i, W_g, W_o, b_f, b_i, b_g, b_o);
    packfc_kernel<<<2048, 256>>>(W_fc);

    // Phase 1: Gx = x @ Wx + bx   (fp16 HMMA, M=16384, N=4096, K=512)
    gemm_f16_bias<<<dim3(32, 128), 256>>>(
        (const __half*)pXh, (const __half*)pWxh, (const float*)pbx,
        (float*)pGx, 16384, 4096, 512);

    // Phase 2: recurrence (persistent, 128 blocks)
    lstm_rec<<<NB2, 512, 16 * 1152 * 4>>>(W_f, W_i, W_g, W_o);

    // Phase 3: out = H2h @ W_fc + b_fc   (fp16 HMMA, M=16384, N=512, K=1024)
    gemm_f16_bias<<<dim3(4, 128), 256>>>(
        (const __half*)pH2h, (const __half*)pWfch, b_fc,
        out, 16384, 512, 1024);
}

// round 10
// speedup vs baseline: 1.2691x; 1.0359x over previous
#include <cuda_runtime.h>
#include <cuda_bf16.h>
#include <cuda_fp16.h>
#include <cstdint>

#define NBG 64    // blocks per batch-group (2 groups x 64 = 128 blocks)

// ------------------------------------------------------------------
// Device-global scratch (allocation-free)
// ------------------------------------------------------------------
__device__ float  d_Gx[(size_t)16384 * 4096];      // x@Wx + bias
__device__ __half d_H2h[(size_t)16384 * 1024];     // h fp16 [b*512+t][j] for final FC
__device__ __half d_Hts[(size_t)513 * 32 * 1024];  // h fp16 [t][b][k_perm]
__device__ __half d_xh[(size_t)16384 * 512];       // x converted to fp16
__device__ __half d_Wxh[(size_t)512 * 4096];       // fp16 input weights, k-pair interleaved
__device__ __half d_Wfch[(size_t)1024 * 512];      // fp16 W_fc, k-pair interleaved
__device__ float  d_bx[4096];                      // packed gate biases
__device__ unsigned d_cnt[1024];                   // per-(group,step) arrival counters

// ------------------------------------------------------------------
// Helpers
// ------------------------------------------------------------------
__device__ __forceinline__ void mma_f16(float c[4],
                                        unsigned a0, unsigned a1, unsigned a2, unsigned a3,
                                        unsigned b0, unsigned b1) {
    asm volatile(
        "mma.sync.aligned.m16n8k16.row.col.f32.f16.f16.f32 "
        "{%0,%1,%2,%3},{%4,%5,%6,%7},{%8,%9},{%0,%1,%2,%3};"
        : "+f"(c[0]), "+f"(c[1]), "+f"(c[2]), "+f"(c[3])
        : "r"(a0), "r"(a1), "r"(a2), "r"(a3), "r"(b0), "r"(b1));
}

__device__ __forceinline__ float tanh_a(float x) {
    float y;
    asm("tanh.approx.f32 %0, %1;" : "=f"(y) : "f"(x));
    return y;
}
__device__ __forceinline__ float sigm(float x) {
    return 0.5f * tanh_a(0.5f * x) + 0.5f;
}

// k-permutation of the fp16 h layout (verified in R5-R9)
__device__ __forceinline__ int perm32(int j) {
    int tg = (j & 7) >> 1;
    int a  = (j & 31) >> 4;
    return (j & ~31) + tg * 8 + a * 4 + (j & 1) + 2 * ((j & 15) >> 3);
}

// ------------------------------------------------------------------
// Init: zero h_0 slab and counters (every launch/replay)
// ------------------------------------------------------------------
__global__ void init_kernel() {
    int idx = blockIdx.x * blockDim.x + threadIdx.x;
    if (idx < 16384) ((unsigned*)d_Hts)[idx] = 0u;   // 32768 halves
    if (idx < 1024) d_cnt[idx] = 0u;
}

// ------------------------------------------------------------------
// Convert x to fp16 (2 floats / thread)
// ------------------------------------------------------------------
__global__ void xconv_kernel(const float* __restrict__ x) {
    int idx = blockIdx.x * blockDim.x + threadIdx.x;
    float2 v = *(const float2*)(x + 2 * (size_t)idx);
    ((__half2*)d_xh)[idx] = __floats2half2_rn(v.x, v.y);
}

// ------------------------------------------------------------------
// Pack fp16 Wx (k-pair interleaved, N=4096) + gate biases
// ------------------------------------------------------------------
__global__ void pack_kernel(const float* __restrict__ Wf, const float* __restrict__ Wi,
                            const float* __restrict__ Wg, const float* __restrict__ Wo,
                            const float* __restrict__ bf, const float* __restrict__ bi,
                            const float* __restrict__ bg, const float* __restrict__ bo) {
    int idx = blockIdx.x * blockDim.x + threadIdx.x;
    if (idx < 512 * 1024) {
        int k = idx >> 10, j = idx & 1023;
        size_t base = ((size_t)(k >> 1) * 4096) * 2 + (k & 1);
        d_Wxh[base + (size_t)(j) * 2]        = __float2half_rn(Wf[idx]);
        d_Wxh[base + (size_t)(j + 1024) * 2] = __float2half_rn(Wi[idx]);
        d_Wxh[base + (size_t)(j + 2048) * 2] = __float2half_rn(Wg[idx]);
        d_Wxh[base + (size_t)(j + 3072) * 2] = __float2half_rn(Wo[idx]);
    }
    if (idx < 1024) {
        d_bx[idx]        = bf[idx];
        d_bx[idx + 1024] = bi[idx];
        d_bx[idx + 2048] = bg[idx];
        d_bx[idx + 3072] = bo[idx];
    }
}

// ------------------------------------------------------------------
// Pack fp16 W_fc (k-pair interleaved, N=512)
// ------------------------------------------------------------------
__global__ void packfc_kernel(const float* __restrict__ Wfc) {
    int idx = blockIdx.x * blockDim.x + threadIdx.x;   // 0 .. 524287
    int k = idx >> 9, j = idx & 511;
    d_Wfch[(((size_t)(k >> 1) * 512) + j) * 2 + (k & 1)] = __float2half_rn(Wfc[idx]);
}

// ------------------------------------------------------------------
// Generic fp16 GEMM: C[M,N] = A[M,K] @ B[K,N] + bias[N]
// A row-major fp16, B k-pair interleaved fp16, C fp32.
// 128x128x32 tiles, 8 warps (warp 64x32). M%128==0, N%128==0, K%32==0.
// ------------------------------------------------------------------
__global__ void __launch_bounds__(256) gemm_f16_bias(
    const __half* __restrict__ A, const __half* __restrict__ Bp,
    const float* __restrict__ bias, float* __restrict__ C,
    int M, int N, int K) {
    __shared__ __half sAh[128 * 40];
    __shared__ __half sBh[16 * 272];

    const int tid = threadIdx.x;
    const int w = tid >> 5, lane = tid & 31;
    const int g = lane >> 2, tig = lane & 3;
    const int wm = (w >> 2) * 64, wn = (w & 3) * 32;
    const int m0 = blockIdx.y * 128, n0 = blockIdx.x * 128;

    float Cr[4][4][4];
#pragma unroll
    for (int a = 0; a < 4; a++)
#pragma unroll
        for (int b = 0; b < 4; b++)
#pragma unroll
            for (int c = 0; c < 4; c++) Cr[a][b][c] = 0.f;

    const int nk = K / 32;
    for (int kc = 0; kc < nk; kc++) {
        const int k0 = kc * 32;
        __syncthreads();
#pragma unroll
        for (int i = 0; i < 2; i++) {
            int lin = tid + i * 256;
            int r = lin >> 2, q = lin & 3;
            *(uint4*)(sAh + r * 40 + q * 8) =
                *(const uint4*)(A + (size_t)(m0 + r) * K + k0 + q * 8);
        }
#pragma unroll
        for (int i = 0; i < 2; i++) {
            int lin = tid + i * 256;
            int k2r = lin >> 5, c4 = lin & 31;
            *(uint4*)(sBh + k2r * 272 + c4 * 8) =
                *(const uint4*)(Bp + ((size_t)((k0 >> 1) + k2r) * N + n0 + c4 * 4) * 2);
        }
        __syncthreads();

#pragma unroll
        for (int kt = 0; kt < 2; kt++) {
            unsigned bf_[4][2];
#pragma unroll
            for (int nt = 0; nt < 4; nt++) {
                int jc = wn + nt * 8 + g;
                bf_[nt][0] = *(const unsigned*)(sBh + (kt * 8 + tig) * 272 + jc * 2);
                bf_[nt][1] = *(const unsigned*)(sBh + (kt * 8 + tig + 4) * 272 + jc * 2);
            }
#pragma unroll
            for (int mt = 0; mt < 4; mt++) {
                int ro = (wm + mt * 16 + g) * 40 + kt * 16 + 2 * tig;
                unsigned a0 = *(const unsigned*)(sAh + ro);
                unsigned a1 = *(const unsigned*)(sAh + ro + 8 * 40);
                unsigned a2 = *(const unsigned*)(sAh + ro + 8);
                unsigned a3 = *(const unsigned*)(sAh + ro + 8 * 40 + 8);
#pragma unroll
                for (int nt = 0; nt < 4; nt++)
                    mma_f16(Cr[mt][nt], a0, a1, a2, a3, bf_[nt][0], bf_[nt][1]);
            }
        }
    }

#pragma unroll
    for (int mt = 0; mt < 4; mt++) {
#pragma unroll
        for (int nt = 0; nt < 4; nt++) {
            int row = m0 + wm + mt * 16 + g;
            int col = n0 + wn + nt * 8 + 2 * tig;
            float bx = bias[col], by = bias[col + 1];
            float2 v0 = make_float2(Cr[mt][nt][0] + bx, Cr[mt][nt][1] + by);
            float2 v1 = make_float2(Cr[mt][nt][2] + bx, Cr[mt][nt][3] + by);
            *(float2*)(C + (size_t)row * N + col) = v0;
            *(float2*)(C + (size_t)(row + 8) * N + col) = v1;
        }
    }
}

// ------------------------------------------------------------------
// Persistent recurrent kernel, BATCH-SPLIT: 2 independent groups of
// 64 blocks; group g owns batch rows [16g, 16g+16) and synchronizes
// ONLY within itself (own counters; R7's proven counter-poll scheme).
// Block bk (in group) owns hidden units [bk*16, bk*16+16) x 4 gates.
// Warp w covers K-slice [w*64, w*64+64), all 64 gate-cols (M=16,
// N=64, K=64 -> 32 HMMAs, 4 LDG.128). Wr[4][8][2] = 64 regs.
// Partials: 16 smem regions, unit-gate-contiguous for float4 reduce.
// ------------------------------------------------------------------
__global__ void __launch_bounds__(512) lstm_rec(
    const float* __restrict__ Wf, const float* __restrict__ Wi,
    const float* __restrict__ Wg, const float* __restrict__ Wo) {
    extern __shared__ float sPart[];   // 16 regions x 16 rows x 68 floats

    const int tid = threadIdx.x;
    const int w = tid >> 5, lane = tid & 31;
    const int gq = lane >> 2, tig = lane & 3;
    const int kw = w * 64;
    const int bid = blockIdx.x;
    const int grp = bid >> 6;          // batch group 0/1
    const int bk  = bid & 63;          // block within group
    const int b0g = grp * 16;          // batch base row

    // ---- Preload weights as fp16x2 B-fragments ----
    // nt = gate*2 + h8 : col = bk*16 + h8*8 + gq, gate in Wp order
    const float* Wp[4] = {Wf, Wi, Wg, Wo};
    unsigned Wr[4][8][2];
#pragma unroll
    for (int kt = 0; kt < 4; kt++) {
#pragma unroll
        for (int nt = 0; nt < 8; nt++) {
            int gate = nt >> 1, h8 = nt & 1;
            const float* ws = Wp[gate]
                + (size_t)(512 + kw + kt * 16 + 2 * tig) * 1024 + bk * 16 + h8 * 8 + gq;
            __half2 lo = __floats2half2_rn(__ldg(ws), __ldg(ws + 1024));
            __half2 hi = __floats2half2_rn(__ldg(ws + 8 * 1024), __ldg(ws + 9 * 1024));
            Wr[kt][nt][0] = *(unsigned*)&lo;
            Wr[kt][nt][1] = *(unsigned*)&hi;
        }
    }

    // State-thread mapping (first 256 threads): b_ = tid/16, uu = tid%16
    const int b_ = (tid >> 4) & 15, uu = tid & 15;
    const bool is_state = tid < 256;
    float creg = 0.f;
    const int j = bk * 16 + uu;
    const int ppos = perm32(j);
    const int bglob = b0g + b_;

    // Incremented pointers
    const __half* hrd = d_Hts + (size_t)b0g * 1024 + kw + tig * 8;        // += 32768
    __half* hwr = d_Hts + 32768 + (size_t)bglob * 1024 + ppos;            // += 32768
    const float* gxp = d_Gx + (size_t)(bglob * 512) * 4096 + j;           // += 4096
    __half* h2p = d_H2h + (size_t)(bglob * 512) * 1024 + j;               // += 1024
    unsigned* cntp = d_cnt + grp * 512;                                    // += 1

    // Prefetch Gx for step 0
    float gx0 = 0.f, gx1 = 0.f, gx2 = 0.f, gx3 = 0.f;
    if (is_state) {
        gx0 = __ldcs(gxp);
        gx1 = __ldcs(gxp + 1024);
        gx2 = __ldcs(gxp + 2048);
        gx3 = __ldcs(gxp + 3072);
    }

    for (int t = 0; t < 512; t++) {
        // ---- h loads (4 x LDG.128) + HMMA (M=16, N=64, K=64) ----
        float Cr[8][4];
#pragma unroll
        for (int nt = 0; nt < 8; nt++)
#pragma unroll
            for (int c = 0; c < 4; c++) Cr[nt][c] = 0.f;

#pragma unroll
        for (int kb = 0; kb < 2; kb++) {
            uint4 v0 = __ldcg((const uint4*)(hrd + kb * 32 + gq * 1024));
            uint4 v1 = __ldcg((const uint4*)(hrd + kb * 32 + (gq + 8) * 1024));
#pragma unroll
            for (int nt = 0; nt < 8; nt++)
                mma_f16(Cr[nt], v0.x, v1.x, v0.y, v1.y,
                        Wr[2 * kb][nt][0], Wr[2 * kb][nt][1]);
#pragma unroll
            for (int nt = 0; nt < 8; nt++)
                mma_f16(Cr[nt], v0.z, v1.z, v0.w, v1.w,
                        Wr[2 * kb + 1][nt][0], Wr[2 * kb + 1][nt][1]);
        }

        // ---- Write partials: region w, [row][unit*4+gate] layout ----
        {
            float* sp = sPart + w * 1088;
#pragma unroll
            for (int nt = 0; nt < 8; nt++) {
                int gate = nt >> 1, h8 = nt & 1;
                int u0 = h8 * 8 + 2 * tig;
                sp[gq * 68 + u0 * 4 + gate]             = Cr[nt][0];
                sp[gq * 68 + (u0 + 1) * 4 + gate]       = Cr[nt][1];
                sp[(gq + 8) * 68 + u0 * 4 + gate]       = Cr[nt][2];
                sp[(gq + 8) * 68 + (u0 + 1) * 4 + gate] = Cr[nt][3];
            }
        }
        __syncthreads();

        // ---- Final reduce (16 x LDS.128) + gates + state update ----
        if (is_state) {
            const float4* rp = (const float4*)(sPart + b_ * 68 + uu * 4);
            float4 s0 = rp[0], s1 = rp[272];   // 1088 floats = 272 float4
#pragma unroll
            for (int r = 2; r < 16; r += 2) {
                float4 a = rp[r * 272], b = rp[(r + 1) * 272];
                s0.x += a.x; s0.y += a.y; s0.z += a.z; s0.w += a.w;
                s1.x += b.x; s1.y += b.y; s1.z += b.z; s1.w += b.w;
            }
            float F = s0.x + s1.x + gx0;
            float I = s0.y + s1.y + gx1;
            float G = s0.z + s1.z + gx2;
            float O = s0.w + s1.w + gx3;
            creg = sigm(F) * creg + sigm(I) * tanh_a(G);
            float h = sigm(O) * tanh_a(creg);

            __half hh = __float2half_rn(h);
            *hwr = hh;
            *h2p = hh;

            // Prefetch Gx for step t+1 (hidden behind the barrier)
            gxp += 4096;
            if (t < 511) {
                gx0 = __ldcs(gxp);
                gx1 = __ldcs(gxp + 1024);
                gx2 = __ldcs(gxp + 2048);
                gx3 = __ldcs(gxp + 3072);
            }
        }
        __syncthreads();   // h stores + sPart reads complete

        // ---- Group barrier (R7 topology: atomic + counter poll) ----
        if (tid == 0) {
            unsigned ret;
            asm volatile("atom.acq_rel.gpu.add.u32 %0, [%1], %2;"
                         : "=r"(ret) : "l"(cntp), "r"(1u) : "memory");
            if (ret + 1u < NBG) {
                unsigned v;
                do {
                    asm volatile("ld.acquire.gpu.u32 %0, [%1];"
                                 : "=r"(v) : "l"(cntp) : "memory");
                } while (v < NBG);
            }
        }
        __syncthreads();

        hrd += 32768; hwr += 32768; h2p += 1024; cntp += 1;
    }
}

// ------------------------------------------------------------------
// Launch sequence (graph-capturable: kernel launches only)
// ------------------------------------------------------------------
extern "C" void kernel_launch(void* const* d_in, const int* in_sizes, int n_in,
                              void* d_out, int out_size) {
    const float* x    = (const float*)d_in[0];
    const float* W_f  = (const float*)d_in[1];
    const float* b_f  = (const float*)d_in[2];
    const float* W_i  = (const float*)d_in[3];
    const float* b_i  = (const float*)d_in[4];
    const float* W_g  = (const float*)d_in[5];
    const float* b_g  = (const float*)d_in[6];
    const float* W_o  = (const float*)d_in[7];
    const float* b_o  = (const float*)d_in[8];
    const float* W_fc = (const float*)d_in[9];
    const float* b_fc = (const float*)d_in[10];
    float* out = (float*)d_out;

    void *pGx, *pH2h, *pXh, *pWxh, *pWfch, *pbx;
    cudaGetSymbolAddress(&pGx, d_Gx);
    cudaGetSymbolAddress(&pH2h, d_H2h);
    cudaGetSymbolAddress(&pXh, d_xh);
    cudaGetSymbolAddress(&pWxh, d_Wxh);
    cudaGetSymbolAddress(&pWfch, d_Wfch);
    cudaGetSymbolAddress(&pbx, d_bx);

    static bool attr_set = false;
    if (!attr_set) {
        cudaFuncSetAttribute(lstm_rec, cudaFuncAttributeMaxDynamicSharedMemorySize,
                             16 * 1088 * 4);
        attr_set = true;
    }

    init_kernel<<<128, 256>>>();
    xconv_kernel<<<16384, 256>>>(x);
    pack_kernel<<<2048, 256>>>(W_f, W_i, W_g, W_o, b_f, b_i, b_g, b_o);
    packfc_kernel<<<2048, 256>>>(W_fc);

    // Phase 1: Gx = x @ Wx + bx   (fp16 HMMA, M=16384, N=4096, K=512)
    gemm_f16_bias<<<dim3(32, 128), 256>>>(
        (const __half*)pXh, (const __half*)pWxh, (const float*)pbx,
        (float*)pGx, 16384, 4096, 512);

    // Phase 2: recurrence (persistent, 2 groups x 64 blocks)
    lstm_rec<<<128, 512, 16 * 1088 * 4>>>(W_f, W_i, W_g, W_o);

    // Phase 3: out = H2h @ W_fc + b_fc   (fp16 HMMA, M=16384, N=512, K=1024)
    gemm_f16_bias<<<dim3(4, 128), 256>>>(
        (const __half*)pH2h, (const __half*)pWfch, b_fc,
        out, 16384, 512, 1024);
}

// round 11
// speedup vs baseline: 1.3276x; 1.0461x over previous
#include <cuda_runtime.h>
#include <cuda_bf16.h>
#include <cuda_fp16.h>
#include <cstdint>

#define NB2 128   // persistent blocks in recurrent kernel (best measured)

// ------------------------------------------------------------------
// Device-global scratch (allocation-free)
// ------------------------------------------------------------------
__device__ float  d_Gx[(size_t)16384 * 4096];      // x@Wx + bias
__device__ __half d_H2h[(size_t)16384 * 1024];     // h fp16 [b*512+t][j] for final FC
__device__ __half d_Hts[(size_t)513 * 32 * 1024];  // h fp16 [t][b][k_perm]
__device__ __half d_xh[(size_t)16384 * 512];       // x converted to fp16
__device__ __half d_Wxh[(size_t)512 * 4096];       // fp16 input weights, k-pair interleaved
__device__ __half d_Wfch[(size_t)1024 * 512];      // fp16 W_fc, k-pair interleaved
__device__ float  d_bx[4096];                      // packed gate biases
__device__ unsigned d_cnt[512];                    // per-step arrival counters

// ------------------------------------------------------------------
// Helpers
// ------------------------------------------------------------------
__device__ __forceinline__ void mma_f16(float c[4],
                                        unsigned a0, unsigned a1, unsigned a2, unsigned a3,
                                        unsigned b0, unsigned b1) {
    asm volatile(
        "mma.sync.aligned.m16n8k16.row.col.f32.f16.f16.f32 "
        "{%0,%1,%2,%3},{%4,%5,%6,%7},{%8,%9},{%0,%1,%2,%3};"
        : "+f"(c[0]), "+f"(c[1]), "+f"(c[2]), "+f"(c[3])
        : "r"(a0), "r"(a1), "r"(a2), "r"(a3), "r"(b0), "r"(b1));
}

__device__ __forceinline__ void ldsm_x4(unsigned& r0, unsigned& r1,
                                        unsigned& r2, unsigned& r3,
                                        const __half* p) {
    unsigned addr = (unsigned)__cvta_generic_to_shared(p);
    asm volatile("ldmatrix.sync.aligned.m8n8.x4.shared.b16 {%0,%1,%2,%3}, [%4];"
                 : "=r"(r0), "=r"(r1), "=r"(r2), "=r"(r3) : "r"(addr));
}

__device__ __forceinline__ float tanh_a(float x) {
    float y;
    asm("tanh.approx.f32 %0, %1;" : "=f"(y) : "f"(x));
    return y;
}
__device__ __forceinline__ float sigm(float x) {
    return 0.5f * tanh_a(0.5f * x) + 0.5f;
}

// k-permutation of the fp16 h layout (verified in R5-R10)
__device__ __forceinline__ int perm32(int j) {
    int tg = (j & 7) >> 1;
    int a  = (j & 31) >> 4;
    return (j & ~31) + tg * 8 + a * 4 + (j & 1) + 2 * ((j & 15) >> 3);
}

// ------------------------------------------------------------------
// Init: zero h_0 slab and counters (every launch/replay)
// ------------------------------------------------------------------
__global__ void init_kernel() {
    int idx = blockIdx.x * blockDim.x + threadIdx.x;
    if (idx < 16384) ((unsigned*)d_Hts)[idx] = 0u;   // 32768 halves
    if (idx < 512) d_cnt[idx] = 0u;
}

// ------------------------------------------------------------------
// Convert x to fp16 (2 floats / thread)
// ------------------------------------------------------------------
__global__ void xconv_kernel(const float* __restrict__ x) {
    int idx = blockIdx.x * blockDim.x + threadIdx.x;
    float2 v = *(const float2*)(x + 2 * (size_t)idx);
    ((__half2*)d_xh)[idx] = __floats2half2_rn(v.x, v.y);
}

// ------------------------------------------------------------------
// Pack fp16 Wx (k-pair interleaved, N=4096) + gate biases
// ------------------------------------------------------------------
__global__ void pack_kernel(const float* __restrict__ Wf, const float* __restrict__ Wi,
                            const float* __restrict__ Wg, const float* __restrict__ Wo,
                            const float* __restrict__ bf, const float* __restrict__ bi,
                            const float* __restrict__ bg, const float* __restrict__ bo) {
    int idx = blockIdx.x * blockDim.x + threadIdx.x;
    if (idx < 512 * 1024) {
        int k = idx >> 10, j = idx & 1023;
        size_t base = ((size_t)(k >> 1) * 4096) * 2 + (k & 1);
        d_Wxh[base + (size_t)(j) * 2]        = __float2half_rn(Wf[idx]);
        d_Wxh[base + (size_t)(j + 1024) * 2] = __float2half_rn(Wi[idx]);
        d_Wxh[base + (size_t)(j + 2048) * 2] = __float2half_rn(Wg[idx]);
        d_Wxh[base + (size_t)(j + 3072) * 2] = __float2half_rn(Wo[idx]);
    }
    if (idx < 1024) {
        d_bx[idx]        = bf[idx];
        d_bx[idx + 1024] = bi[idx];
        d_bx[idx + 2048] = bg[idx];
        d_bx[idx + 3072] = bo[idx];
    }
}

// ------------------------------------------------------------------
// Pack fp16 W_fc (k-pair interleaved, N=512)
// ------------------------------------------------------------------
__global__ void packfc_kernel(const float* __restrict__ Wfc) {
    int idx = blockIdx.x * blockDim.x + threadIdx.x;   // 0 .. 524287
    int k = idx >> 9, j = idx & 511;
    d_Wfch[(((size_t)(k >> 1) * 512) + j) * 2 + (k & 1)] = __float2half_rn(Wfc[idx]);
}

// ------------------------------------------------------------------
// Generic fp16 GEMM: C[M,N] = A[M,K] @ B[K,N] + bias[N]
// A row-major fp16, B k-pair interleaved fp16, C fp32.
// 128x128x32 tiles, 8 warps (warp 64x32). A-fragments via ldmatrix.x4.
// ------------------------------------------------------------------
__global__ void __launch_bounds__(256) gemm_f16_bias(
    const __half* __restrict__ A, const __half* __restrict__ Bp,
    const float* __restrict__ bias, float* __restrict__ C,
    int M, int N, int K) {
    __shared__ __half sAh[128 * 40];   // 128 rows x 32 halves (+8 pad)
    __shared__ __half sBh[16 * 272];   // 16 k2-rows x 128 cols x 2 (+16 pad)

    const int tid = threadIdx.x;
    const int w = tid >> 5, lane = tid & 31;
    const int g = lane >> 2, tig = lane & 3;
    const int wm = (w >> 2) * 64, wn = (w & 3) * 32;
    const int m0 = blockIdx.y * 128, n0 = blockIdx.x * 128;

    // ldmatrix per-lane row/col for A fragments
    const int rA = wm + (lane & 7) + ((lane >> 3) & 1) * 8;
    const int cA = ((lane >> 4) & 1) * 8;

    float Cr[4][4][4];
#pragma unroll
    for (int a = 0; a < 4; a++)
#pragma unroll
        for (int b = 0; b < 4; b++)
#pragma unroll
            for (int c = 0; c < 4; c++) Cr[a][b][c] = 0.f;

    const int nk = K / 32;
    for (int kc = 0; kc < nk; kc++) {
        const int k0 = kc * 32;
        __syncthreads();
#pragma unroll
        for (int i = 0; i < 2; i++) {
            int lin = tid + i * 256;
            int r = lin >> 2, q = lin & 3;
            *(uint4*)(sAh + r * 40 + q * 8) =
                *(const uint4*)(A + (size_t)(m0 + r) * K + k0 + q * 8);
        }
#pragma unroll
        for (int i = 0; i < 2; i++) {
            int lin = tid + i * 256;
            int k2r = lin >> 5, c4 = lin & 31;
            *(uint4*)(sBh + k2r * 272 + c4 * 8) =
                *(const uint4*)(Bp + ((size_t)((k0 >> 1) + k2r) * N + n0 + c4 * 4) * 2);
        }
        __syncthreads();

#pragma unroll
        for (int kt = 0; kt < 2; kt++) {
            unsigned bf_[4][2];
#pragma unroll
            for (int nt = 0; nt < 4; nt++) {
                int jc = wn + nt * 8 + g;
                bf_[nt][0] = *(const unsigned*)(sBh + (kt * 8 + tig) * 272 + jc * 2);
                bf_[nt][1] = *(const unsigned*)(sBh + (kt * 8 + tig + 4) * 272 + jc * 2);
            }
#pragma unroll
            for (int mt = 0; mt < 4; mt++) {
                unsigned a0, a1, a2, a3;
                ldsm_x4(a0, a1, a2, a3,
                        sAh + (rA + mt * 16) * 40 + kt * 16 + cA);
#pragma unroll
                for (int nt = 0; nt < 4; nt++)
                    mma_f16(Cr[mt][nt], a0, a1, a2, a3, bf_[nt][0], bf_[nt][1]);
            }
        }
    }

#pragma unroll
    for (int mt = 0; mt < 4; mt++) {
#pragma unroll
        for (int nt = 0; nt < 4; nt++) {
            int row = m0 + wm + mt * 16 + g;
            int col = n0 + wn + nt * 8 + 2 * tig;
            float bx = bias[col], by = bias[col + 1];
            float2 v0 = make_float2(Cr[mt][nt][0] + bx, Cr[mt][nt][1] + by);
            float2 v1 = make_float2(Cr[mt][nt][2] + bx, Cr[mt][nt][3] + by);
            *(float2*)(C + (size_t)row * N + col) = v0;
            *(float2*)(C + (size_t)(row + 8) * N + col) = v1;
        }
    }
}

// ------------------------------------------------------------------
// Persistent recurrent kernel. 128 blocks x 512 threads (16 warps).
// Compute structure + counter-poll sync = R7 (best measured, 2119us).
// NEW: the (BAR -> tid0 poll -> BAR) tail is replaced by an smem
// release flag: state threads bar.sync(1,256); tid0 does the R7
// atomic + counter poll, then st.release.cta.shared sflag = t+1.
// All warps spin on ld.acquire.cta.shared at the loop top — two full
// 512-thread BARs removed from the per-step critical path, and MMA
// warps launch next-step LDGs the moment the flag lands.
// Hazards: sPart WAR + h(t+1) reads are ordered through the flag
// (tid0 publishes only after bar.sync(1,256) = all state reads and
// h stores done, and after the global counter shows all blocks).
// ------------------------------------------------------------------
__global__ void __launch_bounds__(512) lstm_rec(
    const float* __restrict__ Wf, const float* __restrict__ Wi,
    const float* __restrict__ Wg, const float* __restrict__ Wo) {
    extern __shared__ float sPart[];   // 16 regions x 32 rows x 36 floats
    __shared__ unsigned sflag;

    const int tid = threadIdx.x;
    const int w = tid >> 5, lane = tid & 31;
    const int g = lane >> 2, tig = lane & 3;
    const int kw = w * 64;
    const int bk = blockIdx.x;

    if (tid == 0) sflag = 0u;

    // ---- Preload weights as fp16x2 B-fragments (true k order) ----
    const float* Wp[4] = {Wf, Wi, Wg, Wo};
    unsigned Wr[4][4][2];
#pragma unroll
    for (int kt = 0; kt < 4; kt++) {
#pragma unroll
        for (int nt = 0; nt < 4; nt++) {
            const float* ws = Wp[nt] + (size_t)(512 + kw + kt * 16 + 2 * tig) * 1024 + bk * 8 + g;
            __half2 lo = __floats2half2_rn(__ldg(ws), __ldg(ws + 1024));
            __half2 hi = __floats2half2_rn(__ldg(ws + 8 * 1024), __ldg(ws + 9 * 1024));
            Wr[kt][nt][0] = *(unsigned*)&lo;
            Wr[kt][nt][1] = *(unsigned*)&hi;
        }
    }

    // State-thread mapping (first 256 threads): b = tid/8, uu = tid%8
    const int b_ = (tid >> 3) & 31, uu = tid & 7;
    const bool is_state = tid < 256;
    float creg = 0.f;
    const int j = bk * 8 + uu;
    const int ppos = perm32(j);

    // Incremented pointers
    const __half* hrd = d_Hts + kw + tig * 8;                           // += 32768
    __half* hwr = d_Hts + 32768 + (size_t)b_ * 1024 + ppos;             // += 32768
    const float* gxp = d_Gx + (size_t)(b_ * 512) * 4096 + bk * 8 + uu;  // += 4096
    __half* h2p = d_H2h + (size_t)(b_ * 512) * 1024 + bk * 8 + uu;      // += 1024
    unsigned* cntp = d_cnt;                                              // += 1
    const unsigned sfa = (unsigned)__cvta_generic_to_shared(&sflag);

    __syncthreads();   // sflag init + weight preload complete

    // Prefetch Gx for step 0
    float gx0 = 0.f, gx1 = 0.f, gx2 = 0.f, gx3 = 0.f;
    if (is_state) {
        gx0 = __ldcs(gxp);
        gx1 = __ldcs(gxp + 1024);
        gx2 = __ldcs(gxp + 2048);
        gx3 = __ldcs(gxp + 3072);
    }

    for (int t = 0; t < 512; t++) {
        // ---- Per-warp wait on the block's release flag ----
        if (t > 0) {
            unsigned v;
            do {
                asm volatile("ld.acquire.cta.shared.u32 %0, [%1];"
                             : "=r"(v) : "r"(sfa) : "memory");
            } while (v < (unsigned)t);
        }

        // ---- Front-batched h loads: 8 x LDG.128 (max MLP) ----
        uint4 V[2][2][2];   // [kb][mt][row g / g+8]
#pragma unroll
        for (int kb = 0; kb < 2; kb++)
#pragma unroll
            for (int mt = 0; mt < 2; mt++) {
                V[kb][mt][0] = __ldcg((const uint4*)(hrd + kb * 32 + (mt * 16 + g) * 1024));
                V[kb][mt][1] = __ldcg((const uint4*)(hrd + kb * 32 + (mt * 16 + g + 8) * 1024));
            }

        // ---- h_t @ Wh_slice (fp16 HMMA, fp32 accum) ----
        float Cr[2][4][4];
#pragma unroll
        for (int mt = 0; mt < 2; mt++)
#pragma unroll
            for (int nt = 0; nt < 4; nt++)
#pragma unroll
                for (int c = 0; c < 4; c++) Cr[mt][nt][c] = 0.f;

#pragma unroll
        for (int kb = 0; kb < 2; kb++) {
#pragma unroll
            for (int mt = 0; mt < 2; mt++) {
                const uint4& v0 = V[kb][mt][0];
                const uint4& v1 = V[kb][mt][1];
#pragma unroll
                for (int nt = 0; nt < 4; nt++)
                    mma_f16(Cr[mt][nt], v0.x, v1.x, v0.y, v1.y,
                            Wr[2 * kb][nt][0], Wr[2 * kb][nt][1]);
#pragma unroll
                for (int nt = 0; nt < 4; nt++)
                    mma_f16(Cr[mt][nt], v0.z, v1.z, v0.w, v1.w,
                            Wr[2 * kb + 1][nt][0], Wr[2 * kb + 1][nt][1]);
            }
        }

        // ---- Write partials: region w, gate-contiguous layout ----
        {
            float* sp = sPart + w * 1152;
#pragma unroll
            for (int mt = 0; mt < 2; mt++) {
#pragma unroll
                for (int nt = 0; nt < 4; nt++) {
                    int row = mt * 16 + g, c = 2 * tig;
                    sp[row * 36 + c * 4 + nt]             = Cr[mt][nt][0];
                    sp[row * 36 + (c + 1) * 4 + nt]       = Cr[mt][nt][1];
                    sp[(row + 8) * 36 + c * 4 + nt]       = Cr[mt][nt][2];
                    sp[(row + 8) * 36 + (c + 1) * 4 + nt] = Cr[mt][nt][3];
                }
            }
        }
        __syncthreads();   // all partials visible to the reduce

        // ---- State epilogue + arrival + release (warps 0-7 only) ----
        if (is_state) {
            const float4* rp = (const float4*)sPart + (b_ * 9 + uu);
            float4 s0 = rp[0], s1 = rp[288];
#pragma unroll
            for (int r = 2; r < 16; r += 2) {
                float4 a = rp[r * 288], b = rp[(r + 1) * 288];
                s0.x += a.x; s0.y += a.y; s0.z += a.z; s0.w += a.w;
                s1.x += b.x; s1.y += b.y; s1.z += b.z; s1.w += b.w;
            }
            float F = s0.x + s1.x + gx0;
            float I = s0.y + s1.y + gx1;
            float G = s0.z + s1.z + gx2;
            float O = s0.w + s1.w + gx3;
            creg = sigm(F) * creg + sigm(I) * tanh_a(G);
            float h = sigm(O) * tanh_a(creg);

            __half hh = __float2half_rn(h);
            *hwr = hh;
            *h2p = hh;

            // Prefetch Gx for step t+1 (hidden behind the wait)
            gxp += 4096;
            if (t < 511) {
                gx0 = __ldcs(gxp);
                gx1 = __ldcs(gxp + 1024);
                gx2 = __ldcs(gxp + 2048);
                gx3 = __ldcs(gxp + 3072);
            }

            // All state threads done (sPart reads + h stores) -> arrive
            asm volatile("bar.sync 1, 256;" ::: "memory");
            if (tid == 0) {
                unsigned ret;
                asm volatile("atom.acq_rel.gpu.add.u32 %0, [%1], %2;"
                             : "=r"(ret) : "l"(cntp), "r"(1u) : "memory");
                if (ret + 1u < NB2) {
                    unsigned v;
                    do {
                        asm volatile("ld.acquire.gpu.u32 %0, [%1];"
                                     : "=r"(v) : "l"(cntp) : "memory");
                    } while (v < NB2);
                }
                asm volatile("st.release.cta.shared.u32 [%0], %1;"
                             :: "r"(sfa), "r"((unsigned)(t + 1)) : "memory");
            }
        }

        hrd += 32768; hwr += 32768; h2p += 1024; cntp += 1;
    }
}

// ------------------------------------------------------------------
// Launch sequence (graph-capturable: kernel launches only)
// ------------------------------------------------------------------
extern "C" void kernel_launch(void* const* d_in, const int* in_sizes, int n_in,
                              void* d_out, int out_size) {
    const float* x    = (const float*)d_in[0];
    const float* W_f  = (const float*)d_in[1];
    const float* b_f  = (const float*)d_in[2];
    const float* W_i  = (const float*)d_in[3];
    const float* b_i  = (const float*)d_in[4];
    const float* W_g  = (const float*)d_in[5];
    const float* b_g  = (const float*)d_in[6];
    const float* W_o  = (const float*)d_in[7];
    const float* b_o  = (const float*)d_in[8];
    const float* W_fc = (const float*)d_in[9];
    const float* b_fc = (const float*)d_in[10];
    float* out = (float*)d_out;

    void *pGx, *pH2h, *pXh, *pWxh, *pWfch, *pbx;
    cudaGetSymbolAddress(&pGx, d_Gx);
    cudaGetSymbolAddress(&pH2h, d_H2h);
    cudaGetSymbolAddress(&pXh, d_xh);
    cudaGetSymbolAddress(&pWxh, d_Wxh);
    cudaGetSymbolAddress(&pWfch, d_Wfch);
    cudaGetSymbolAddress(&pbx, d_bx);

    static bool attr_set = false;
    if (!attr_set) {
        cudaFuncSetAttribute(lstm_rec, cudaFuncAttributeMaxDynamicSharedMemorySize,
                             16 * 1152 * 4);
        attr_set = true;
    }

    init_kernel<<<128, 256>>>();
    xconv_kernel<<<16384, 256>>>(x);
    pack_kernel<<<2048, 256>>>(W_f, W_i, W_g, W_o, b_f, b_i, b_g, b_o);
    packfc_kernel<<<2048, 256>>>(W_fc);

    // Phase 1: Gx = x @ Wx + bx   (fp16 HMMA, M=16384, N=4096, K=512)
    gemm_f16_bias<<<dim3(32, 128), 256>>>(
        (const __half*)pXh, (const __half*)pWxh, (const float*)pbx,
        (float*)pGx, 16384, 4096, 512);

    // Phase 2: recurrence (persistent, 128 blocks)
    lstm_rec<<<NB2, 512, 16 * 1152 * 4>>>(W_f, W_i, W_g, W_o);

    // Phase 3: out = H2h @ W_fc + b_fc   (fp16 HMMA, M=16384, N=512, K=1024)
    gemm_f16_bias<<<dim3(4, 128), 256>>>(
        (const __half*)pH2h, (const __half*)pWfch, b_fc,
        out, 16384, 512, 1024);
}

// round 12
// speedup vs baseline: 1.4315x; 1.0782x over previous
#include <cuda_runtime.h>
#include <cuda_bf16.h>
#include <cuda_fp16.h>
#include <cstdint>

#define NB2 128   // persistent blocks in recurrent kernel (best measured)

// ------------------------------------------------------------------
// Device-global scratch (allocation-free)
// ------------------------------------------------------------------
__device__ float  d_Gx[(size_t)16384 * 4096];      // x@Wx + bias
__device__ __half d_H2h[(size_t)16384 * 1024];     // h fp16 [b*512+t][j] for final FC
__device__ __half d_Hts[(size_t)513 * 32 * 1024];  // h fp16 [t][b][k_perm]
__device__ __half d_xh[(size_t)16384 * 512];       // x converted to fp16
__device__ __half d_Wxh[(size_t)512 * 4096];       // fp16 input weights, k-pair interleaved
__device__ __half d_Wfch[(size_t)1024 * 512];      // fp16 W_fc, k-pair interleaved
__device__ float  d_bx[4096];                      // packed gate biases
__device__ unsigned d_cnt[512];                    // per-step arrival counters

// ------------------------------------------------------------------
// Helpers
// ------------------------------------------------------------------
__device__ __forceinline__ void mma_f16(float c[4],
                                        unsigned a0, unsigned a1, unsigned a2, unsigned a3,
                                        unsigned b0, unsigned b1) {
    asm volatile(
        "mma.sync.aligned.m16n8k16.row.col.f32.f16.f16.f32 "
        "{%0,%1,%2,%3},{%4,%5,%6,%7},{%8,%9},{%0,%1,%2,%3};"
        : "+f"(c[0]), "+f"(c[1]), "+f"(c[2]), "+f"(c[3])
        : "r"(a0), "r"(a1), "r"(a2), "r"(a3), "r"(b0), "r"(b1));
}

__device__ __forceinline__ void ldsm_x4(unsigned& r0, unsigned& r1,
                                        unsigned& r2, unsigned& r3,
                                        const __half* p) {
    unsigned addr = (unsigned)__cvta_generic_to_shared(p);
    asm volatile("ldmatrix.sync.aligned.m8n8.x4.shared.b16 {%0,%1,%2,%3}, [%4];"
                 : "=r"(r0), "=r"(r1), "=r"(r2), "=r"(r3) : "r"(addr));
}

__device__ __forceinline__ float tanh_a(float x) {
    float y;
    asm("tanh.approx.f32 %0, %1;" : "=f"(y) : "f"(x));
    return y;
}
__device__ __forceinline__ float sigm(float x) {
    return 0.5f * tanh_a(0.5f * x) + 0.5f;
}

// k-permutation of the fp16 h layout (verified in R5-R11)
__device__ __forceinline__ int perm32(int j) {
    int tg = (j & 7) >> 1;
    int a  = (j & 31) >> 4;
    return (j & ~31) + tg * 8 + a * 4 + (j & 1) + 2 * ((j & 15) >> 3);
}

// ------------------------------------------------------------------
// Init: zero h_0 slab and counters (every launch/replay)
// ------------------------------------------------------------------
__global__ void init_kernel() {
    int idx = blockIdx.x * blockDim.x + threadIdx.x;
    if (idx < 16384) ((unsigned*)d_Hts)[idx] = 0u;   // 32768 halves
    if (idx < 512) d_cnt[idx] = 0u;
}

// ------------------------------------------------------------------
// Convert x to fp16 (2 floats / thread)
// ------------------------------------------------------------------
__global__ void xconv_kernel(const float* __restrict__ x) {
    int idx = blockIdx.x * blockDim.x + threadIdx.x;
    float2 v = *(const float2*)(x + 2 * (size_t)idx);
    ((__half2*)d_xh)[idx] = __floats2half2_rn(v.x, v.y);
}

// ------------------------------------------------------------------
// Pack fp16 Wx (k-pair interleaved, N=4096) + gate biases
// ------------------------------------------------------------------
__global__ void pack_kernel(const float* __restrict__ Wf, const float* __restrict__ Wi,
                            const float* __restrict__ Wg, const float* __restrict__ Wo,
                            const float* __restrict__ bf, const float* __restrict__ bi,
                            const float* __restrict__ bg, const float* __restrict__ bo) {
    int idx = blockIdx.x * blockDim.x + threadIdx.x;
    if (idx < 512 * 1024) {
        int k = idx >> 10, j = idx & 1023;
        size_t base = ((size_t)(k >> 1) * 4096) * 2 + (k & 1);
        d_Wxh[base + (size_t)(j) * 2]        = __float2half_rn(Wf[idx]);
        d_Wxh[base + (size_t)(j + 1024) * 2] = __float2half_rn(Wi[idx]);
        d_Wxh[base + (size_t)(j + 2048) * 2] = __float2half_rn(Wg[idx]);
        d_Wxh[base + (size_t)(j + 3072) * 2] = __float2half_rn(Wo[idx]);
    }
    if (idx < 1024) {
        d_bx[idx]        = bf[idx];
        d_bx[idx + 1024] = bi[idx];
        d_bx[idx + 2048] = bg[idx];
        d_bx[idx + 3072] = bo[idx];
    }
}

// ------------------------------------------------------------------
// Pack fp16 W_fc (k-pair interleaved, N=512)
// ------------------------------------------------------------------
__global__ void packfc_kernel(const float* __restrict__ Wfc) {
    int idx = blockIdx.x * blockDim.x + threadIdx.x;   // 0 .. 524287
    int k = idx >> 9, j = idx & 511;
    d_Wfch[(((size_t)(k >> 1) * 512) + j) * 2 + (k & 1)] = __float2half_rn(Wfc[idx]);
}

// ------------------------------------------------------------------
// Generic fp16 GEMM: C[M,N] = A[M,K] @ B[K,N] + bias[N]
// A row-major fp16, B k-pair interleaved fp16, C fp32.
// 128x128x32 tiles, 8 warps (warp 64x32). A-fragments via ldmatrix.x4.
// NEW: register-staged pipeline — chunk k+1 is LDG'd into registers
// while chunk k computes, so global latency hides behind the MMAs.
// ------------------------------------------------------------------
__global__ void __launch_bounds__(256) gemm_f16_bias(
    const __half* __restrict__ A, const __half* __restrict__ Bp,
    const float* __restrict__ bias, float* __restrict__ C,
    int M, int N, int K) {
    __shared__ __half sAh[128 * 40];   // 128 rows x 32 halves (+8 pad)
    __shared__ __half sBh[16 * 272];   // 16 k2-rows x 128 cols x 2 (+16 pad)

    const int tid = threadIdx.x;
    const int w = tid >> 5, lane = tid & 31;
    const int g = lane >> 2, tig = lane & 3;
    const int wm = (w >> 2) * 64, wn = (w & 3) * 32;
    const int m0 = blockIdx.y * 128, n0 = blockIdx.x * 128;

    // ldmatrix per-lane row/col for A fragments
    const int rA = wm + (lane & 7) + ((lane >> 3) & 1) * 8;
    const int cA = ((lane >> 4) & 1) * 8;

    // Per-thread slab load coordinates (same for LDG and STS)
    const int arr0 = tid >> 2,           aq0 = tid & 3;          // A chunk i=0
    const int arr1 = (tid + 256) >> 2,   aq1 = tid & 3;          // A chunk i=1
    const int bk0 = tid >> 5,            bc0 = tid & 31;         // B chunk i=0
    const int bk1 = (tid + 256) >> 5,    bc1 = tid & 31;         // B chunk i=1

    const __half* gA0 = A + (size_t)(m0 + arr0) * K + aq0 * 8;
    const __half* gA1 = A + (size_t)(m0 + arr1) * K + aq1 * 8;
    const __half* gB0 = Bp + ((size_t)bk0 * N + n0 + bc0 * 4) * 2;
    const __half* gB1 = Bp + ((size_t)bk1 * N + n0 + bc1 * 4) * 2;

    float Cr[4][4][4];
#pragma unroll
    for (int a = 0; a < 4; a++)
#pragma unroll
        for (int b = 0; b < 4; b++)
#pragma unroll
            for (int c = 0; c < 4; c++) Cr[a][b][c] = 0.f;

    const int nk = K / 32;

    // Prologue: stage chunk 0
    uint4 stA0 = *(const uint4*)(gA0);
    uint4 stA1 = *(const uint4*)(gA1);
    uint4 stB0 = *(const uint4*)(gB0);
    uint4 stB1 = *(const uint4*)(gB1);

    for (int kc = 0; kc < nk; kc++) {
        __syncthreads();   // previous compute done; smem free
        *(uint4*)(sAh + arr0 * 40 + aq0 * 8) = stA0;
        *(uint4*)(sAh + arr1 * 40 + aq1 * 8) = stA1;
        *(uint4*)(sBh + bk0 * 272 + bc0 * 8) = stB0;
        *(uint4*)(sBh + bk1 * 272 + bc1 * 8) = stB1;
        __syncthreads();   // slab ready

        if (kc + 1 < nk) {
            int k0 = (kc + 1) * 32;
            stA0 = *(const uint4*)(gA0 + k0);
            stA1 = *(const uint4*)(gA1 + k0);
            stB0 = *(const uint4*)(gB0 + (size_t)(k0 >> 1) * N * 2);
            stB1 = *(const uint4*)(gB1 + (size_t)(k0 >> 1) * N * 2);
        }

#pragma unroll
        for (int kt = 0; kt < 2; kt++) {
            unsigned bf_[4][2];
#pragma unroll
            for (int nt = 0; nt < 4; nt++) {
                int jc = wn + nt * 8 + g;
                bf_[nt][0] = *(const unsigned*)(sBh + (kt * 8 + tig) * 272 + jc * 2);
                bf_[nt][1] = *(const unsigned*)(sBh + (kt * 8 + tig + 4) * 272 + jc * 2);
            }
#pragma unroll
            for (int mt = 0; mt < 4; mt++) {
                unsigned a0, a1, a2, a3;
                ldsm_x4(a0, a1, a2, a3,
                        sAh + (rA + mt * 16) * 40 + kt * 16 + cA);
#pragma unroll
                for (int nt = 0; nt < 4; nt++)
                    mma_f16(Cr[mt][nt], a0, a1, a2, a3, bf_[nt][0], bf_[nt][1]);
            }
        }
    }

#pragma unroll
    for (int mt = 0; mt < 4; mt++) {
#pragma unroll
        for (int nt = 0; nt < 4; nt++) {
            int row = m0 + wm + mt * 16 + g;
            int col = n0 + wn + nt * 8 + 2 * tig;
            float bx = bias[col], by = bias[col + 1];
            float2 v0 = make_float2(Cr[mt][nt][0] + bx, Cr[mt][nt][1] + by);
            float2 v1 = make_float2(Cr[mt][nt][2] + bx, Cr[mt][nt][3] + by);
            *(float2*)(C + (size_t)row * N + col) = v0;
            *(float2*)(C + (size_t)(row + 8) * N + col) = v1;
        }
    }
}

// ------------------------------------------------------------------
// Persistent recurrent kernel. 128 blocks x 512 threads (16 warps).
// Structure = R11 (best measured, 2073us): smem-flag release, state
// named barrier + tid0 atomic/counter-poll, fp16 HMMA + k_perm h.
// ONLY change: the Gx(t+1) prefetch moves AFTER the barrier arrival
// (it was delaying every block's arrival — and tid0's atomic — by
// ~20-30 cyc on the global critical chain; it still has >800 cyc of
// slack before consumption next step).
// ------------------------------------------------------------------
__global__ void __launch_bounds__(512) lstm_rec(
    const float* __restrict__ Wf, const float* __restrict__ Wi,
    const float* __restrict__ Wg, const float* __restrict__ Wo) {
    extern __shared__ float sPart[];   // 16 regions x 32 rows x 36 floats
    __shared__ unsigned sflag;

    const int tid = threadIdx.x;
    const int w = tid >> 5, lane = tid & 31;
    const int g = lane >> 2, tig = lane & 3;
    const int kw = w * 64;
    const int bk = blockIdx.x;

    if (tid == 0) sflag = 0u;

    // ---- Preload weights as fp16x2 B-fragments (true k order) ----
    const float* Wp[4] = {Wf, Wi, Wg, Wo};
    unsigned Wr[4][4][2];
#pragma unroll
    for (int kt = 0; kt < 4; kt++) {
#pragma unroll
        for (int nt = 0; nt < 4; nt++) {
            const float* ws = Wp[nt] + (size_t)(512 + kw + kt * 16 + 2 * tig) * 1024 + bk * 8 + g;
            __half2 lo = __floats2half2_rn(__ldg(ws), __ldg(ws + 1024));
            __half2 hi = __floats2half2_rn(__ldg(ws + 8 * 1024), __ldg(ws + 9 * 1024));
            Wr[kt][nt][0] = *(unsigned*)&lo;
            Wr[kt][nt][1] = *(unsigned*)&hi;
        }
    }

    // State-thread mapping (first 256 threads): b = tid/8, uu = tid%8
    const int b_ = (tid >> 3) & 31, uu = tid & 7;
    const bool is_state = tid < 256;
    float creg = 0.f;
    const int j = bk * 8 + uu;
    const int ppos = perm32(j);

    // Incremented pointers
    const __half* hrd = d_Hts + kw + tig * 8;                           // += 32768
    __half* hwr = d_Hts + 32768 + (size_t)b_ * 1024 + ppos;             // += 32768
    const float* gxp = d_Gx + (size_t)(b_ * 512) * 4096 + bk * 8 + uu;  // += 4096
    __half* h2p = d_H2h + (size_t)(b_ * 512) * 1024 + bk * 8 + uu;      // += 1024
    unsigned* cntp = d_cnt;                                              // += 1
    const unsigned sfa = (unsigned)__cvta_generic_to_shared(&sflag);

    __syncthreads();   // sflag init + weight preload complete

    // Prefetch Gx for step 0
    float gx0 = 0.f, gx1 = 0.f, gx2 = 0.f, gx3 = 0.f;
    if (is_state) {
        gx0 = __ldcs(gxp);
        gx1 = __ldcs(gxp + 1024);
        gx2 = __ldcs(gxp + 2048);
        gx3 = __ldcs(gxp + 3072);
    }

    for (int t = 0; t < 512; t++) {
        // ---- Per-warp wait on the block's release flag ----
        if (t > 0) {
            unsigned v;
            do {
                asm volatile("ld.acquire.cta.shared.u32 %0, [%1];"
                             : "=r"(v) : "r"(sfa) : "memory");
            } while (v < (unsigned)t);
        }

        // ---- Front-batched h loads: 8 x LDG.128 (max MLP) ----
        uint4 V[2][2][2];   // [kb][mt][row g / g+8]
#pragma unroll
        for (int kb = 0; kb < 2; kb++)
#pragma unroll
            for (int mt = 0; mt < 2; mt++) {
                V[kb][mt][0] = __ldcg((const uint4*)(hrd + kb * 32 + (mt * 16 + g) * 1024));
                V[kb][mt][1] = __ldcg((const uint4*)(hrd + kb * 32 + (mt * 16 + g + 8) * 1024));
            }

        // ---- h_t @ Wh_slice (fp16 HMMA, fp32 accum) ----
        float Cr[2][4][4];
#pragma unroll
        for (int mt = 0; mt < 2; mt++)
#pragma unroll
            for (int nt = 0; nt < 4; nt++)
#pragma unroll
                for (int c = 0; c < 4; c++) Cr[mt][nt][c] = 0.f;

#pragma unroll
        for (int kb = 0; kb < 2; kb++) {
#pragma unroll
            for (int mt = 0; mt < 2; mt++) {
                const uint4& v0 = V[kb][mt][0];
                const uint4& v1 = V[kb][mt][1];
#pragma unroll
                for (int nt = 0; nt < 4; nt++)
                    mma_f16(Cr[mt][nt], v0.x, v1.x, v0.y, v1.y,
                            Wr[2 * kb][nt][0], Wr[2 * kb][nt][1]);
#pragma unroll
                for (int nt = 0; nt < 4; nt++)
                    mma_f16(Cr[mt][nt], v0.z, v1.z, v0.w, v1.w,
                            Wr[2 * kb + 1][nt][0], Wr[2 * kb + 1][nt][1]);
            }
        }

        // ---- Write partials: region w, gate-contiguous layout ----
        {
            float* sp = sPart + w * 1152;
#pragma unroll
            for (int mt = 0; mt < 2; mt++) {
#pragma unroll
                for (int nt = 0; nt < 4; nt++) {
                    int row = mt * 16 + g, c = 2 * tig;
                    sp[row * 36 + c * 4 + nt]             = Cr[mt][nt][0];
                    sp[row * 36 + (c + 1) * 4 + nt]       = Cr[mt][nt][1];
                    sp[(row + 8) * 36 + c * 4 + nt]       = Cr[mt][nt][2];
                    sp[(row + 8) * 36 + (c + 1) * 4 + nt] = Cr[mt][nt][3];
                }
            }
        }
        __syncthreads();   // all partials visible to the reduce

        // ---- State epilogue + arrival + release (warps 0-7 only) ----
        if (is_state) {
            const float4* rp = (const float4*)sPart + (b_ * 9 + uu);
            float4 s0 = rp[0], s1 = rp[288];
#pragma unroll
            for (int r = 2; r < 16; r += 2) {
                float4 a = rp[r * 288], b = rp[(r + 1) * 288];
                s0.x += a.x; s0.y += a.y; s0.z += a.z; s0.w += a.w;
                s1.x += b.x; s1.y += b.y; s1.z += b.z; s1.w += b.w;
            }
            float F = s0.x + s1.x + gx0;
            float I = s0.y + s1.y + gx1;
            float G = s0.z + s1.z + gx2;
            float O = s0.w + s1.w + gx3;
            creg = sigm(F) * creg + sigm(I) * tanh_a(G);
            float h = sigm(O) * tanh_a(creg);

            __half hh = __float2half_rn(h);
            *hwr = hh;
            *h2p = hh;

            // All state threads done (sPart reads + h stores) -> arrive
            asm volatile("bar.sync 1, 256;" ::: "memory");
            if (tid == 0) {
                unsigned ret;
                asm volatile("atom.acq_rel.gpu.add.u32 %0, [%1], %2;"
                             : "=r"(ret) : "l"(cntp), "r"(1u) : "memory");
                if (ret + 1u < NB2) {
                    unsigned v;
                    do {
                        asm volatile("ld.acquire.gpu.u32 %0, [%1];"
                                     : "=r"(v) : "l"(cntp) : "memory");
                    } while (v < NB2);
                }
                asm volatile("st.release.cta.shared.u32 [%0], %1;"
                             :: "r"(sfa), "r"((unsigned)(t + 1)) : "memory");
            }

            // Prefetch Gx for step t+1 (off the arrival critical path)
            gxp += 4096;
            if (t < 511) {
                gx0 = __ldcs(gxp);
                gx1 = __ldcs(gxp + 1024);
                gx2 = __ldcs(gxp + 2048);
                gx3 = __ldcs(gxp + 3072);
            }
        }

        hrd += 32768; hwr += 32768; h2p += 1024; cntp += 1;
    }
}

// ------------------------------------------------------------------
// Launch sequence (graph-capturable: kernel launches only)
// ------------------------------------------------------------------
extern "C" void kernel_launch(void* const* d_in, const int* in_sizes, int n_in,
                              void* d_out, int out_size) {
    const float* x    = (const float*)d_in[0];
    const float* W_f  = (const float*)d_in[1];
    const float* b_f  = (const float*)d_in[2];
    const float* W_i  = (const float*)d_in[3];
    const float* b_i  = (const float*)d_in[4];
    const float* W_g  = (const float*)d_in[5];
    const float* b_g  = (const float*)d_in[6];
    const float* W_o  = (const float*)d_in[7];
    const float* b_o  = (const float*)d_in[8];
    const float* W_fc = (const float*)d_in[9];
    const float* b_fc = (const float*)d_in[10];
    float* out = (float*)d_out;

    void *pGx, *pH2h, *pXh, *pWxh, *pWfch, *pbx;
    cudaGetSymbolAddress(&pGx, d_Gx);
    cudaGetSymbolAddress(&pH2h, d_H2h);
    cudaGetSymbolAddress(&pXh, d_xh);
    cudaGetSymbolAddress(&pWxh, d_Wxh);
    cudaGetSymbolAddress(&pWfch, d_Wfch);
    cudaGetSymbolAddress(&pbx, d_bx);

    static bool attr_set = false;
    if (!attr_set) {
        cudaFuncSetAttribute(lstm_rec, cudaFuncAttributeMaxDynamicSharedMemorySize,
                             16 * 1152 * 4);
        attr_set = true;
    }

    init_kernel<<<128, 256>>>();
    xconv_kernel<<<16384, 256>>>(x);
    pack_kernel<<<2048, 256>>>(W_f, W_i, W_g, W_o, b_f, b_i, b_g, b_o);
    packfc_kernel<<<2048, 256>>>(W_fc);

    // Phase 1: Gx = x @ Wx + bx   (fp16 HMMA, M=16384, N=4096, K=512)
    gemm_f16_bias<<<dim3(32, 128), 256>>>(
        (const __half*)pXh, (const __half*)pWxh, (const float*)pbx,
        (float*)pGx, 16384, 4096, 512);

    // Phase 2: recurrence (persistent, 128 blocks)
    lstm_rec<<<NB2, 512, 16 * 1152 * 4>>>(W_f, W_i, W_g, W_o);

    // Phase 3: out = H2h @ W_fc + b_fc   (fp16 HMMA, M=16384, N=512, K=1024)
    gemm_f16_bias<<<dim3(4, 128), 256>>>(
        (const __half*)pH2h, (const __half*)pWfch, b_fc,
        out, 16384, 512, 1024);
}